// round 7
// baseline (speedup 1.0000x reference)
#include <cuda_runtime.h>
#include <mma.h>
#include <cstdint>

using namespace nvcuda;

#define NN 50000
#define NP 50048        // padded rows: 391 * 128
#define NE 800000
#define RREL 8
#define NSEG (NN * RREL)   // 400000
#define KA 2320            // augmented K: 2048 gathered + 256 self + 1 bias + 15 pad
#define NSTAGE 4

// ---------------- static device scratch ----------------
__device__ int   g_cnt[NSEG];
__device__ float g_inv[NSEG];
__device__ int   g_soff[NSEG + 1];
__device__ int   g_scur[NSEG];
__device__ int   g_seidx[NE];
__device__ int   g_bsum[512];
__device__ float g_Y[(size_t)NP * KA];      // 464 MB
__device__ float g_h1[NP * 256];
__device__ float g_h2s[NP * 128];
__device__ float g_H[2 * NP * 256];         // Hs | Hd
__device__ float g_wt[1021952];             // pre-rounded stacked weights

#define OFF_B1 0         // [2320 x 256]: W1 flat | root1 | bias1 row | zeros
#define OFF_B2 593920    // [2320 x 128]: W2 flat | root2 | bias2 row | zeros
#define OFF_M1 890880    // mlpW1 [512 x 256]

__device__ __forceinline__ float to_tf32(float x) {
    float y;
    asm("cvt.rna.tf32.f32 %0, %1;" : "=f"(y) : "f"(x));
    return y;
}

#define CP16(dst, src) \
    asm volatile("cp.async.cg.shared.global [%0], [%1], 16;" :: "r"(dst), "l"(src))
#define CP_COMMIT() asm volatile("cp.async.commit_group;" ::: "memory")
template <int N>
__device__ __forceinline__ void cp_wait() {
    asm volatile("cp.async.wait_group %0;" :: "n"(N) : "memory");
}
__device__ __forceinline__ uint32_t sptr(const void* p) {
    return (uint32_t)__cvta_generic_to_shared(p);
}

// ================= wmma tf32 GEMM: reg-double-buffer A + cp.async B =================
// C[M, 128*gridDim.y] = A[M,K] @ B[K,N]; optional fused relu on output.
#define ALD 20
#define BLD 132
__global__ void __launch_bounds__(256, 2) twmma_kernel(const float* __restrict__ A,
                                                       const float* __restrict__ B,
                                                       float* __restrict__ C,
                                                       int M, int K, int lda, int ldb, int ldc,
                                                       long sB, long sC, int do_relu) {
    extern __shared__ float smem[];
    float* sA = smem;                       // [2][128*ALD]
    float* sB_ = smem + 2 * 128 * ALD;      // [NSTAGE][16*BLD]

    B += (long)blockIdx.z * sB;
    C += (long)blockIdx.z * sC;
    int bm = blockIdx.x * 128;
    int bn = blockIdx.y * 128;

    int tid = threadIdx.x;
    int w = tid >> 5;
    int wm = w & 1;
    int wn = w >> 1;

    wmma::fragment<wmma::accumulator, 16, 16, 8, float> acc[4][2];
#pragma unroll
    for (int i = 0; i < 4; i++)
#pragma unroll
        for (int j = 0; j < 2; j++) wmma::fill_fragment(acc[i][j], 0.f);

    int ar = tid >> 1, ah = (tid & 1) * 8;
    bool ok = (bm + ar) < M;
    const float* aB = A + (size_t)(bm + ar) * lda + ah;
    float4 ra0, ra1;

    int brow = (tid * 2) >> 5, bc4 = (tid * 2) & 31;
    const float* bBase = B + (size_t)brow * ldb + bn + bc4 * 4;

#define LOADA(kt) do { \
        ra0 = ok ? __ldg((const float4*)(aB + (kt)))     : make_float4(0.f, 0.f, 0.f, 0.f); \
        ra1 = ok ? __ldg((const float4*)(aB + (kt) + 4)) : make_float4(0.f, 0.f, 0.f, 0.f); \
    } while (0)
#define STOREA(buf) do { \
        float* s = sA + (buf) * 128 * ALD + ar * ALD + ah; \
        s[0] = to_tf32(ra0.x); s[1] = to_tf32(ra0.y); s[2] = to_tf32(ra0.z); s[3] = to_tf32(ra0.w); \
        s[4] = to_tf32(ra1.x); s[5] = to_tf32(ra1.y); s[6] = to_tf32(ra1.z); s[7] = to_tf32(ra1.w); \
    } while (0)
#define ISSUEB(stage, kt) do { \
        uint32_t d = sptr(sB_ + (stage) * 16 * BLD + brow * BLD + bc4 * 4); \
        const float* sgp = bBase + (size_t)(kt) * ldb; \
        CP16(d, sgp); CP16(d + 16, sgp + 4); \
    } while (0)

    int nk = K >> 4;
#pragma unroll
    for (int s = 0; s < NSTAGE - 1; s++) {
        if (s < nk) ISSUEB(s, s << 4);
        CP_COMMIT();
    }
    LOADA(0);
    STOREA(0);

    for (int i = 0; i < nk; i++) {
        if (i + 1 < nk) LOADA((i + 1) << 4);
        cp_wait<NSTAGE - 2>();
        __syncthreads();
        if (i + NSTAGE - 1 < nk) ISSUEB((i + NSTAGE - 1) % NSTAGE, (i + NSTAGE - 1) << 4);
        CP_COMMIT();

        float* sa = sA + (i & 1) * 128 * ALD;
        float* sb = sB_ + (i % NSTAGE) * 16 * BLD;
#pragma unroll
        for (int ks = 0; ks < 16; ks += 8) {
            wmma::fragment<wmma::matrix_a, 16, 16, 8, wmma::precision::tf32, wmma::row_major> af[4];
            wmma::fragment<wmma::matrix_b, 16, 16, 8, wmma::precision::tf32, wmma::row_major> bf[2];
#pragma unroll
            for (int x = 0; x < 4; x++)
                wmma::load_matrix_sync(af[x], sa + (wm * 64 + x * 16) * ALD + ks, ALD);
#pragma unroll
            for (int y = 0; y < 2; y++)
                wmma::load_matrix_sync(bf[y], sb + ks * BLD + wn * 32 + y * 16, BLD);
#pragma unroll
            for (int x = 0; x < 4; x++)
#pragma unroll
                for (int y = 0; y < 2; y++)
                    wmma::mma_sync(acc[x][y], af[x], bf[y], acc[x][y]);
        }
        if (i + 1 < nk) STOREA((i + 1) & 1);
    }

    if (do_relu) {
#pragma unroll
        for (int i = 0; i < 4; i++)
#pragma unroll
            for (int j = 0; j < 2; j++)
#pragma unroll
                for (int t = 0; t < acc[i][j].num_elements; t++)
                    acc[i][j].x[t] = fmaxf(acc[i][j].x[t], 0.f);
    }

#pragma unroll
    for (int i = 0; i < 4; i++)
#pragma unroll
        for (int j = 0; j < 2; j++) {
            size_t off = (size_t)(bm + wm * 64 + i * 16) * ldc + bn + wn * 32 + j * 16;
            wmma::store_matrix_sync(C + off, acc[i][j], ldc, wmma::mem_row_major);
        }
#undef LOADA
#undef STOREA
#undef ISSUEB
}

// ================= fused edge MLP (unchanged) =================
#define EALD 20
#define EBLD 260
__global__ void __launch_bounds__(256, 2) edge_fused_kernel(const int* __restrict__ srcv,
                                                            const int* __restrict__ dstv,
                                                            const float* __restrict__ etext,
                                                            const float* __restrict__ Wt,
                                                            const float* __restrict__ b1v,
                                                            const float* __restrict__ w2v,
                                                            const float* __restrict__ b2v,
                                                            const float* __restrict__ Hs,
                                                            const float* __restrict__ Hd,
                                                            float* __restrict__ logits) {
    extern __shared__ float smem[];
    float* sA = smem;
    float* sB = smem + 2 * 64 * EALD;
    float* sC = smem;

    int tid = threadIdx.x;
    int w = tid >> 5, lane = tid & 31;
    int bm = blockIdx.x * 64;

    wmma::fragment<wmma::accumulator, 16, 16, 8, float> acc[4][2];
#pragma unroll
    for (int i = 0; i < 4; i++)
#pragma unroll
        for (int j = 0; j < 2; j++) wmma::fill_fragment(acc[i][j], 0.f);

    int ar = tid >> 2, aq = (tid & 3) * 4;
    const float* aB = etext + (size_t)(bm + ar) * 256 + aq;
    float4 ra;

    int brow = (tid * 4) >> 6, bc4 = (tid * 4) & 63;
    const float* bBase = Wt + (size_t)brow * 256 + bc4 * 4;

#define ELOADA(kt)  do { ra = __ldg((const float4*)(aB + (kt))); } while (0)
#define ESTOREA(buf) do { \
        float* s = sA + (buf) * 64 * EALD + ar * EALD + aq; \
        s[0] = to_tf32(ra.x); s[1] = to_tf32(ra.y); s[2] = to_tf32(ra.z); s[3] = to_tf32(ra.w); \
    } while (0)
#define EISSUEB(stage, kt) do { \
        uint32_t d = sptr(sB + (stage) * 16 * EBLD + brow * EBLD + bc4 * 4); \
        const float* sgp = bBase + (size_t)(kt) * 256; \
        CP16(d, sgp); CP16(d + 16, sgp + 4); CP16(d + 32, sgp + 8); CP16(d + 48, sgp + 12); \
    } while (0)

    const int nk = 16;
#pragma unroll
    for (int s = 0; s < NSTAGE - 1; s++) {
        EISSUEB(s, s << 4);
        CP_COMMIT();
    }
    ELOADA(0);
    ESTOREA(0);

    for (int i = 0; i < nk; i++) {
        if (i + 1 < nk) ELOADA((i + 1) << 4);
        cp_wait<NSTAGE - 2>();
        __syncthreads();
        if (i + NSTAGE - 1 < nk) EISSUEB((i + NSTAGE - 1) % NSTAGE, (i + NSTAGE - 1) << 4);
        CP_COMMIT();

        float* sa = sA + (i & 1) * 64 * EALD;
        float* sb = sB + (i % NSTAGE) * 16 * EBLD;
#pragma unroll
        for (int ks = 0; ks < 16; ks += 8) {
            wmma::fragment<wmma::matrix_a, 16, 16, 8, wmma::precision::tf32, wmma::row_major> af[4];
            wmma::fragment<wmma::matrix_b, 16, 16, 8, wmma::precision::tf32, wmma::row_major> bf[2];
#pragma unroll
            for (int x = 0; x < 4; x++)
                wmma::load_matrix_sync(af[x], sa + (x * 16) * EALD + ks, EALD);
#pragma unroll
            for (int y = 0; y < 2; y++)
                wmma::load_matrix_sync(bf[y], sb + ks * EBLD + w * 32 + y * 16, EBLD);
#pragma unroll
            for (int x = 0; x < 4; x++)
#pragma unroll
                for (int y = 0; y < 2; y++)
                    wmma::mma_sync(acc[x][y], af[x], bf[y], acc[x][y]);
        }
        if (i + 1 < nk) ESTOREA((i + 1) & 1);
    }

    __syncthreads();
#pragma unroll
    for (int i = 0; i < 4; i++)
#pragma unroll
        for (int j = 0; j < 2; j++)
            wmma::store_matrix_sync(sC + (i * 16) * 256 + w * 32 + j * 16, acc[i][j],
                                    256, wmma::mem_row_major);
    __syncthreads();

    int c0 = lane * 8;
    float4 b1a = __ldg((const float4*)(b1v + c0));
    float4 b1b = __ldg((const float4*)(b1v + c0 + 4));
    float4 w2a = __ldg((const float4*)(w2v + c0));
    float4 w2b = __ldg((const float4*)(w2v + c0 + 4));
    float beta = __ldg(b2v);

#pragma unroll
    for (int ei = 0; ei < 8; ei++) {
        int el = w * 8 + ei;
        int e = bm + el;
        int s = __ldg(srcv + e), d = __ldg(dstv + e);
        float4 ca = *(float4*)(sC + el * 256 + c0);
        float4 cb = *(float4*)(sC + el * 256 + c0 + 4);
        float4 hsa = __ldg((const float4*)(Hs + (size_t)s * 256 + c0));
        float4 hsb = __ldg((const float4*)(Hs + (size_t)s * 256 + c0 + 4));
        float4 hda = __ldg((const float4*)(Hd + (size_t)d * 256 + c0));
        float4 hdb = __ldg((const float4*)(Hd + (size_t)d * 256 + c0 + 4));
        float p = 0.f, h;
        h = fmaxf(ca.x + hsa.x + hda.x + b1a.x, 0.f); p = fmaf(h, w2a.x, p);
        h = fmaxf(ca.y + hsa.y + hda.y + b1a.y, 0.f); p = fmaf(h, w2a.y, p);
        h = fmaxf(ca.z + hsa.z + hda.z + b1a.z, 0.f); p = fmaf(h, w2a.z, p);
        h = fmaxf(ca.w + hsa.w + hda.w + b1a.w, 0.f); p = fmaf(h, w2a.w, p);
        h = fmaxf(cb.x + hsb.x + hdb.x + b1b.x, 0.f); p = fmaf(h, w2b.x, p);
        h = fmaxf(cb.y + hsb.y + hdb.y + b1b.y, 0.f); p = fmaf(h, w2b.y, p);
        h = fmaxf(cb.z + hsb.z + hdb.z + b1b.z, 0.f); p = fmaf(h, w2b.z, p);
        h = fmaxf(cb.w + hsb.w + hdb.w + b1b.w, 0.f); p = fmaf(h, w2b.w, p);
#pragma unroll
        for (int off = 16; off > 0; off >>= 1)
            p += __shfl_down_sync(0xffffffffu, p, off);
        if (lane == 0) logits[e] = p + beta;
    }
#undef ELOADA
#undef ESTOREA
#undef EISSUEB
}

// ================= CSR build over (dst, rel) segments =================
__global__ void zeroi_kernel(int* p, int n) {
    int i = blockIdx.x * blockDim.x + threadIdx.x;
    if (i < n) p[i] = 0;
}
__global__ void count_kernel(const int* __restrict__ dstv, const int* __restrict__ etype) {
    int e = blockIdx.x * blockDim.x + threadIdx.x;
    if (e < NE) atomicAdd(&g_cnt[dstv[e] * RREL + etype[e]], 1);
}
__global__ void inv_kernel() {
    int i = blockIdx.x * blockDim.x + threadIdx.x;
    if (i < NSEG) {
        int c = g_cnt[i];
        g_inv[i] = c > 0 ? 1.0f / (float)c : 0.0f;
    }
}
__global__ void scan1_kernel() {
    __shared__ int s[1024];
    int tid = threadIdx.x;
    int i = blockIdx.x * 1024 + tid;
    int v = (i < NSEG) ? g_cnt[i] : 0;
    s[tid] = v;
    __syncthreads();
    for (int o = 1; o < 1024; o <<= 1) {
        int x = (tid >= o) ? s[tid - o] : 0;
        __syncthreads();
        s[tid] += x;
        __syncthreads();
    }
    if (i < NSEG) g_soff[i] = s[tid] - v;   // block-local exclusive
    if (tid == 1023) g_bsum[blockIdx.x] = s[1023];
}
__global__ void scan2_kernel(int nb) {
    __shared__ int s[512];
    int tid = threadIdx.x;
    int v = (tid < nb) ? g_bsum[tid] : 0;
    s[tid] = v;
    __syncthreads();
    for (int o = 1; o < 512; o <<= 1) {
        int x = (tid >= o) ? s[tid - o] : 0;
        __syncthreads();
        s[tid] += x;
        __syncthreads();
    }
    if (tid < nb) g_bsum[tid] = s[tid] - v;  // exclusive block offsets
}
__global__ void scan3_kernel() {
    int i = blockIdx.x * blockDim.x + threadIdx.x;
    if (i < NSEG) g_soff[i] += g_bsum[i >> 10];
    if (i == NSEG) g_soff[NSEG] = NE;
}
__global__ void fill_kernel(const int* __restrict__ srcv, const int* __restrict__ dstv,
                            const int* __restrict__ etype) {
    int e = blockIdx.x * blockDim.x + threadIdx.x;
    if (e >= NE) return;
    int s = dstv[e] * RREL + etype[e];
    int pos = g_soff[s] + atomicAdd(&g_scur[s], 1);
    g_seidx[pos] = srcv[e];
}

// ================= gather into augmented Y =================
// Y[d, r*256 + c] = inv[d,r] * sum_{e in seg} x[src_e][c]    (256 cols, 64 thr/seg)
__global__ void __launch_bounds__(256) gather_kernel(const float* __restrict__ x,
                                                     float* __restrict__ Y) {
    int tid = threadIdx.x;
    int seg = blockIdx.x * 4 + (tid >> 6);
    int c = tid & 63;
    if (seg >= NSEG) return;
    int beg = __ldg(g_soff + seg), end = __ldg(g_soff + seg + 1);
    float4 acc = make_float4(0.f, 0.f, 0.f, 0.f);
    for (int j = beg; j < end; j++) {
        int src = __ldg(g_seidx + j);
        float4 v = __ldg((const float4*)(x + (size_t)src * 256) + c);
        acc.x += v.x; acc.y += v.y; acc.z += v.z; acc.w += v.w;
    }
    float w = __ldg(g_inv + seg);
    acc.x *= w; acc.y *= w; acc.z *= w; acc.w *= w;
    int d = seg >> 3, r = seg & 7;
    *((float4*)(Y + (size_t)d * KA + r * 256) + c) = acc;
}
// Y[d, 2048:2304] = x[d]; Y[d, 2304] = 1; Y[d, 2305:2319] = 0
__global__ void aug_kernel(const float* __restrict__ x, float* __restrict__ Y) {
    int i = blockIdx.x * blockDim.x + threadIdx.x;
    if (i >= NN * 68) return;
    int d = i / 68, j = i % 68;
    float4 v;
    if (j < 64)       v = __ldg((const float4*)(x + (size_t)d * 256) + j);
    else if (j == 64) v = make_float4(1.f, 0.f, 0.f, 0.f);
    else              v = make_float4(0.f, 0.f, 0.f, 0.f);
    *((float4*)(Y + (size_t)d * KA + 2048) + j) = v;
}

// ================= utility =================
__global__ void round_copy_kernel(const float4* __restrict__ src, float4* __restrict__ dst, int n4) {
    int i = blockIdx.x * blockDim.x + threadIdx.x;
    if (i < n4) {
        float4 v = src[i];
        v.x = to_tf32(v.x); v.y = to_tf32(v.y); v.z = to_tf32(v.z); v.w = to_tf32(v.w);
        dst[i] = v;
    }
}
// rows 2304..2319 of a stacked B: row 2304 = bias (tf32), rest 0
__global__ void bias_fill_kernel(const float* __restrict__ bias, float* __restrict__ dst, int nc) {
    int i = blockIdx.x * blockDim.x + threadIdx.x;
    if (i >= 16 * nc) return;
    int row = i / nc, col = i % nc;
    dst[row * nc + col] = (row == 0) ? to_tf32(__ldg(bias + col)) : 0.f;
}
__global__ void copy4_kernel(const float4* __restrict__ src, float4* __restrict__ dst, int n4) {
    int i = blockIdx.x * blockDim.x + threadIdx.x;
    if (i < n4) dst[i] = src[i];
}

// ================= launch =================
extern "C" void kernel_launch(void* const* d_in, const int* in_sizes, int n_in,
                              void* d_out, int out_size) {
    const int*   edge_index = (const int*)d_in[0];
    const int*   etype      = (const int*)d_in[1];
    const float* etext      = (const float*)d_in[2];
    const float* node_emb   = (const float*)d_in[3];
    const float* W1         = (const float*)d_in[4];
    const float* root1      = (const float*)d_in[5];
    const float* b1         = (const float*)d_in[6];
    const float* W2         = (const float*)d_in[7];
    const float* root2      = (const float*)d_in[8];
    const float* b2         = (const float*)d_in[9];
    const float* mlpW1      = (const float*)d_in[10];
    const float* mlpb1      = (const float*)d_in[11];
    const float* mlpW2      = (const float*)d_in[12];
    const float* mlpb2      = (const float*)d_in[13];

    const int* srcv = edge_index;
    const int* dstv = edge_index + NE;
    float* logits = (float*)d_out;
    float* h2out  = (float*)d_out + NE;

    void* p;
    cudaGetSymbolAddress(&p, g_cnt);  int*   cntp = (int*)p;
    cudaGetSymbolAddress(&p, g_scur); int*   curp = (int*)p;
    cudaGetSymbolAddress(&p, g_Y);    float* Y    = (float*)p;
    cudaGetSymbolAddress(&p, g_h1);   float* h1   = (float*)p;
    cudaGetSymbolAddress(&p, g_h2s);  float* h2s  = (float*)p;
    cudaGetSymbolAddress(&p, g_H);    float* H    = (float*)p;
    cudaGetSymbolAddress(&p, g_wt);   float* wt   = (float*)p;

    const int GSMEM = 2 * 128 * ALD * 4 + NSTAGE * 16 * BLD * 4;
    const int ESMEM = 2 * 64 * EALD * 4 + NSTAGE * 16 * EBLD * 4;
    cudaFuncSetAttribute(twmma_kernel, cudaFuncAttributeMaxDynamicSharedMemorySize, GSMEM);
    cudaFuncSetAttribute(edge_fused_kernel, cudaFuncAttributeMaxDynamicSharedMemorySize, ESMEM);

    // ---- stacked, pre-rounded weights ----
    round_copy_kernel<<<512, 256>>>((const float4*)W1, (float4*)(wt + OFF_B1), 524288 / 4);
    round_copy_kernel<<<64, 256>>>((const float4*)root1, (float4*)(wt + OFF_B1 + 524288), 65536 / 4);
    bias_fill_kernel<<<16, 256>>>(b1, wt + OFF_B1 + 2304 * 256, 256);
    round_copy_kernel<<<256, 256>>>((const float4*)W2, (float4*)(wt + OFF_B2), 262144 / 4);
    round_copy_kernel<<<32, 256>>>((const float4*)root2, (float4*)(wt + OFF_B2 + 262144), 32768 / 4);
    bias_fill_kernel<<<8, 256>>>(b2, wt + OFF_B2 + 2304 * 128, 128);
    round_copy_kernel<<<128, 256>>>((const float4*)mlpW1, (float4*)(wt + OFF_M1), 131072 / 4);

    // ---- CSR over (dst, rel) segments ----
    zeroi_kernel<<<(NSEG + 255) / 256, 256>>>(cntp, NSEG);
    zeroi_kernel<<<(NSEG + 255) / 256, 256>>>(curp, NSEG);
    count_kernel<<<(NE + 255) / 256, 256>>>(dstv, etype);
    inv_kernel<<<(NSEG + 255) / 256, 256>>>();
    const int NB = (NSEG + 1023) / 1024;   // 391
    scan1_kernel<<<NB, 1024>>>();
    scan2_kernel<<<1, 512>>>(NB);
    scan3_kernel<<<(NSEG + 256) / 256, 256>>>();
    fill_kernel<<<(NE + 255) / 256, 256>>>(srcv, dstv, etype);

    const int MB = NP / 128;  // 391

    // ---- layer 1: gather(node_emb) -> Y, then fused GEMM+root+bias+relu ----
    gather_kernel<<<NSEG / 4, 256>>>(node_emb, Y);
    aug_kernel<<<(NN * 68 + 255) / 256, 256>>>(node_emb, Y);
    twmma_kernel<<<dim3(MB, 2, 1), 256, GSMEM>>>(Y, wt + OFF_B1, h1,
                                                 NN, KA, KA, 256, 256, 0L, 0L, 1);

    // ---- layer 2 ----
    gather_kernel<<<NSEG / 4, 256>>>(h1, Y);
    aug_kernel<<<(NN * 68 + 255) / 256, 256>>>(h1, Y);
    twmma_kernel<<<dim3(MB, 1, 1), 256, GSMEM>>>(Y, wt + OFF_B2, h2s,
                                                 NN, KA, KA, 128, 128, 0L, 0L, 1);
    copy4_kernel<<<(NN * 32 + 255) / 256, 256>>>((const float4*)h2s, (float4*)h2out, NN * 32);

    // ---- edge MLP: Hs/Hd in one launch (z=2), then fused edge kernel ----
    twmma_kernel<<<dim3(MB, 2, 2), 256, GSMEM>>>(h2s, wt + OFF_M1, H,
                                                 NN, 128, 128, 256, 256,
                                                 32768L, (long)NP * 256, 0);
    edge_fused_kernel<<<NE / 64, 256, ESMEM>>>(srcv, dstv, etext, wt + OFF_M1 + 65536,
                                               mlpb1, mlpW2, mlpb2,
                                               H, H + (size_t)NP * 256, logits);
}

// round 8
// speedup vs baseline: 2.4120x; 2.4120x over previous
#include <cuda_runtime.h>
#include <cuda_fp16.h>
#include <mma.h>
#include <cstdint>

using namespace nvcuda;

#define NN 50000
#define NP 50048        // padded rows: 391 * 128
#define NE 800000
#define RREL 8
#define NSTAGE 4

// ---------------- static device scratch ----------------
__device__ int    g_cnt[NN * RREL];
__device__ float  g_inv[NN * RREL];
__device__ int    g_deg[NN];
__device__ int    g_off[NN + 1];
__device__ int    g_cur[NN];
__device__ int    g_eidx[NE];
__device__ float  g_xW[(size_t)NP * 2048];   // 410 MB; layer-2 reuses
__device__ float  g_agg[NP * 256];           // root GEMM output (base for aggregation)
__device__ float  g_h1[NN * 256];
__device__ float  g_H[2 * (size_t)NP * 256]; // Hs | Hd
__device__ __half g_wt[1015808];             // fp16 weights

#define OFF_W1 0
#define OFF_R1 524288
#define OFF_W2 589824
#define OFF_R2 851968
#define OFF_M1 884736   // mlpW1 (512x256): Hs rows 0:128, Hd 128:256, Wt 256:512

#define CP16(dst, src) \
    asm volatile("cp.async.cg.shared.global [%0], [%1], 16;" :: "r"(dst), "l"(src))
#define CP_COMMIT() asm volatile("cp.async.commit_group;" ::: "memory")
template <int N>
__device__ __forceinline__ void cp_wait() {
    asm volatile("cp.async.wait_group %0;" :: "n"(N) : "memory");
}
__device__ __forceinline__ uint32_t sptr(const void* p) {
    return (uint32_t)__cvta_generic_to_shared(p);
}

// ================= wmma fp16 GEMM: reg-double-buffer A + cp.async B =================
// C[M, 128-blocks] = A[M,K](fp32) @ B[K,N](fp16); block tile 128x128, warp 64x32.
#define ALD 24      // halves
#define BLD 136     // halves
__global__ void __launch_bounds__(256, 2) twmma_kernel(const float* __restrict__ A,
                                                       const __half* __restrict__ B,
                                                       float* __restrict__ C,
                                                       int M, int K, int lda, int ldb, int ldc,
                                                       long sB, long sC) {
    extern __shared__ __half hsm[];
    __half* sA = hsm;                       // [2][128*ALD]
    __half* sB_ = hsm + 2 * 128 * ALD;      // [NSTAGE][16*BLD]

    B += (long)blockIdx.z * sB;
    C += (long)blockIdx.z * sC;
    int bm = blockIdx.x * 128;
    int bn = blockIdx.y * 128;

    int tid = threadIdx.x;
    int w = tid >> 5;
    int wm = w & 1;
    int wn = w >> 1;

    wmma::fragment<wmma::accumulator, 16, 16, 16, float> acc[4][2];
#pragma unroll
    for (int i = 0; i < 4; i++)
#pragma unroll
        for (int j = 0; j < 2; j++) wmma::fill_fragment(acc[i][j], 0.f);

    int ar = tid >> 1, ah = (tid & 1) * 8;
    bool ok = (bm + ar) < M;
    const float* aB = A + (size_t)(bm + ar) * lda + ah;
    float4 ra0, ra1;

    int brow = tid >> 4, bc8 = tid & 15;    // one 16B chunk (8 halves) per thread
    const __half* bBase = B + (size_t)brow * ldb + bn + bc8 * 8;

#define LOADA(kt) do { \
        ra0 = ok ? __ldg((const float4*)(aB + (kt)))     : make_float4(0.f, 0.f, 0.f, 0.f); \
        ra1 = ok ? __ldg((const float4*)(aB + (kt) + 4)) : make_float4(0.f, 0.f, 0.f, 0.f); \
    } while (0)
#define STOREA(buf) do { \
        __half* s = sA + (buf) * 128 * ALD + ar * ALD + ah; \
        ((half2*)s)[0] = __floats2half2_rn(ra0.x, ra0.y); \
        ((half2*)s)[1] = __floats2half2_rn(ra0.z, ra0.w); \
        ((half2*)s)[2] = __floats2half2_rn(ra1.x, ra1.y); \
        ((half2*)s)[3] = __floats2half2_rn(ra1.z, ra1.w); \
    } while (0)
#define ISSUEB(stage, kt) do { \
        uint32_t d = sptr(sB_ + (stage) * 16 * BLD + brow * BLD + bc8 * 8); \
        CP16(d, bBase + (size_t)(kt) * ldb); \
    } while (0)

    int nk = K >> 4;
#pragma unroll
    for (int s = 0; s < NSTAGE - 1; s++) {
        if (s < nk) ISSUEB(s, s << 4);
        CP_COMMIT();
    }
    LOADA(0);
    STOREA(0);

    for (int i = 0; i < nk; i++) {
        if (i + 1 < nk) LOADA((i + 1) << 4);
        cp_wait<NSTAGE - 2>();
        __syncthreads();
        if (i + NSTAGE - 1 < nk) ISSUEB((i + NSTAGE - 1) % NSTAGE, (i + NSTAGE - 1) << 4);
        CP_COMMIT();

        __half* sa = sA + (i & 1) * 128 * ALD;
        __half* sb = sB_ + (i % NSTAGE) * 16 * BLD;
        wmma::fragment<wmma::matrix_a, 16, 16, 16, __half, wmma::row_major> af[4];
        wmma::fragment<wmma::matrix_b, 16, 16, 16, __half, wmma::row_major> bf[2];
#pragma unroll
        for (int x = 0; x < 4; x++)
            wmma::load_matrix_sync(af[x], sa + (wm * 64 + x * 16) * ALD, ALD);
#pragma unroll
        for (int y = 0; y < 2; y++)
            wmma::load_matrix_sync(bf[y], sb + wn * 32 + y * 16, BLD);
#pragma unroll
        for (int x = 0; x < 4; x++)
#pragma unroll
            for (int y = 0; y < 2; y++)
                wmma::mma_sync(acc[x][y], af[x], bf[y], acc[x][y]);

        if (i + 1 < nk) STOREA((i + 1) & 1);
    }

#pragma unroll
    for (int i = 0; i < 4; i++)
#pragma unroll
        for (int j = 0; j < 2; j++) {
            size_t off = (size_t)(bm + wm * 64 + i * 16) * ldc + bn + wn * 32 + j * 16;
            wmma::store_matrix_sync(C + off, acc[i][j], ldc, wmma::mem_row_major);
        }
#undef LOADA
#undef STOREA
#undef ISSUEB
}

// ================= fused edge MLP, fp16 =================
#define EALD 24
#define EBLD 264
__global__ void __launch_bounds__(256, 2) edge_fused_kernel(const int* __restrict__ srcv,
                                                            const int* __restrict__ dstv,
                                                            const float* __restrict__ etext,
                                                            const __half* __restrict__ Wt,
                                                            const float* __restrict__ b1v,
                                                            const float* __restrict__ w2v,
                                                            const float* __restrict__ b2v,
                                                            const float* __restrict__ Hs,
                                                            const float* __restrict__ Hd,
                                                            float* __restrict__ logits) {
    extern __shared__ __half hsm[];
    __half* sA = hsm;                       // [2][64*EALD]
    __half* sB = hsm + 2 * 64 * EALD;       // [NSTAGE][16*EBLD]
    float*  sC = (float*)hsm;               // [64][256] fp32 overlay

    int tid = threadIdx.x;
    int w = tid >> 5, lane = tid & 31;
    int bm = blockIdx.x * 64;

    wmma::fragment<wmma::accumulator, 16, 16, 16, float> acc[4][2];
#pragma unroll
    for (int i = 0; i < 4; i++)
#pragma unroll
        for (int j = 0; j < 2; j++) wmma::fill_fragment(acc[i][j], 0.f);

    int ar = tid >> 2, aq = (tid & 3) * 4;
    const float* aB = etext + (size_t)(bm + ar) * 256 + aq;
    float4 ra;

    int brow = tid >> 4, bc16 = (tid & 15) * 16;   // 16 halves (2 chunks) per thread
    const __half* bBase = Wt + (size_t)brow * 256 + bc16;

#define ELOADA(kt)  do { ra = __ldg((const float4*)(aB + (kt))); } while (0)
#define ESTOREA(buf) do { \
        __half* s = sA + (buf) * 64 * EALD + ar * EALD + aq; \
        ((half2*)s)[0] = __floats2half2_rn(ra.x, ra.y); \
        ((half2*)s)[1] = __floats2half2_rn(ra.z, ra.w); \
    } while (0)
#define EISSUEB(stage, kt) do { \
        uint32_t d = sptr(sB + (stage) * 16 * EBLD + brow * EBLD + bc16); \
        const __half* sgp = bBase + (size_t)(kt) * 256; \
        CP16(d, sgp); CP16(d + 16, sgp + 8); \
    } while (0)

    const int nk = 16;
#pragma unroll
    for (int s = 0; s < NSTAGE - 1; s++) {
        EISSUEB(s, s << 4);
        CP_COMMIT();
    }
    ELOADA(0);
    ESTOREA(0);

    for (int i = 0; i < nk; i++) {
        if (i + 1 < nk) ELOADA((i + 1) << 4);
        cp_wait<NSTAGE - 2>();
        __syncthreads();
        if (i + NSTAGE - 1 < nk) EISSUEB((i + NSTAGE - 1) % NSTAGE, (i + NSTAGE - 1) << 4);
        CP_COMMIT();

        __half* sa = sA + (i & 1) * 64 * EALD;
        __half* sb = sB + (i % NSTAGE) * 16 * EBLD;
        wmma::fragment<wmma::matrix_a, 16, 16, 16, __half, wmma::row_major> af[4];
        wmma::fragment<wmma::matrix_b, 16, 16, 16, __half, wmma::row_major> bf[2];
#pragma unroll
        for (int x = 0; x < 4; x++)
            wmma::load_matrix_sync(af[x], sa + (x * 16) * EALD, EALD);
#pragma unroll
        for (int y = 0; y < 2; y++)
            wmma::load_matrix_sync(bf[y], sb + w * 32 + y * 16, EBLD);
#pragma unroll
        for (int x = 0; x < 4; x++)
#pragma unroll
            for (int y = 0; y < 2; y++)
                wmma::mma_sync(acc[x][y], af[x], bf[y], acc[x][y]);

        if (i + 1 < nk) ESTOREA((i + 1) & 1);
    }

    cp_wait<0>();
    __syncthreads();
#pragma unroll
    for (int i = 0; i < 4; i++)
#pragma unroll
        for (int j = 0; j < 2; j++)
            wmma::store_matrix_sync(sC + (i * 16) * 256 + w * 32 + j * 16, acc[i][j],
                                    256, wmma::mem_row_major);
    __syncthreads();

    int c0 = lane * 8;
    float4 b1a = __ldg((const float4*)(b1v + c0));
    float4 b1b = __ldg((const float4*)(b1v + c0 + 4));
    float4 w2a = __ldg((const float4*)(w2v + c0));
    float4 w2b = __ldg((const float4*)(w2v + c0 + 4));
    float beta = __ldg(b2v);

#pragma unroll
    for (int ei = 0; ei < 8; ei++) {
        int el = w * 8 + ei;
        int e = bm + el;
        int s = __ldg(srcv + e), d = __ldg(dstv + e);
        float4 ca = *(float4*)(sC + el * 256 + c0);
        float4 cb = *(float4*)(sC + el * 256 + c0 + 4);
        float4 hsa = __ldg((const float4*)(Hs + (size_t)s * 256 + c0));
        float4 hsb = __ldg((const float4*)(Hs + (size_t)s * 256 + c0 + 4));
        float4 hda = __ldg((const float4*)(Hd + (size_t)d * 256 + c0));
        float4 hdb = __ldg((const float4*)(Hd + (size_t)d * 256 + c0 + 4));
        float p = 0.f, h;
        h = fmaxf(ca.x + hsa.x + hda.x + b1a.x, 0.f); p = fmaf(h, w2a.x, p);
        h = fmaxf(ca.y + hsa.y + hda.y + b1a.y, 0.f); p = fmaf(h, w2a.y, p);
        h = fmaxf(ca.z + hsa.z + hda.z + b1a.z, 0.f); p = fmaf(h, w2a.z, p);
        h = fmaxf(ca.w + hsa.w + hda.w + b1a.w, 0.f); p = fmaf(h, w2a.w, p);
        h = fmaxf(cb.x + hsb.x + hdb.x + b1b.x, 0.f); p = fmaf(h, w2b.x, p);
        h = fmaxf(cb.y + hsb.y + hdb.y + b1b.y, 0.f); p = fmaf(h, w2b.y, p);
        h = fmaxf(cb.z + hsb.z + hdb.z + b1b.z, 0.f); p = fmaf(h, w2b.z, p);
        h = fmaxf(cb.w + hsb.w + hdb.w + b1b.w, 0.f); p = fmaf(h, w2b.w, p);
#pragma unroll
        for (int off = 16; off > 0; off >>= 1)
            p += __shfl_down_sync(0xffffffffu, p, off);
        if (lane == 0) logits[e] = p + beta;
    }
#undef ELOADA
#undef ESTOREA
#undef EISSUEB
}

// ================= CSR build (by dst) =================
__global__ void zeroi_kernel(int* p, int n) {
    int i = blockIdx.x * blockDim.x + threadIdx.x;
    if (i < n) p[i] = 0;
}
__global__ void count_kernel(const int* __restrict__ dstv, const int* __restrict__ etype) {
    int e = blockIdx.x * blockDim.x + threadIdx.x;
    if (e < NE) atomicAdd(&g_cnt[dstv[e] * RREL + etype[e]], 1);
}
__global__ void inv_deg_kernel() {
    int d = blockIdx.x * blockDim.x + threadIdx.x;
    if (d >= NN) return;
    int tot = 0;
#pragma unroll
    for (int r = 0; r < RREL; r++) {
        int c = g_cnt[d * RREL + r];
        tot += c;
        g_inv[d * RREL + r] = c > 0 ? 1.0f / (float)c : 0.0f;
    }
    g_deg[d] = tot;
}
__global__ void scan_kernel() {
    __shared__ int s[1024];
    __shared__ int carry;
    int tid = threadIdx.x;
    if (tid == 0) carry = 0;
    __syncthreads();
    for (int base = 0; base < NN; base += 1024) {
        int v = (base + tid < NN) ? g_deg[base + tid] : 0;
        s[tid] = v;
        __syncthreads();
        for (int o = 1; o < 1024; o <<= 1) {
            int x = (tid >= o) ? s[tid - o] : 0;
            __syncthreads();
            s[tid] += x;
            __syncthreads();
        }
        if (base + tid < NN) g_off[base + tid] = carry + s[tid] - v;
        __syncthreads();
        if (tid == 0) carry += s[1023];
        __syncthreads();
    }
    if (tid == 0) g_off[NN] = carry;
}
__global__ void fill_kernel(const int* __restrict__ srcv, const int* __restrict__ dstv,
                            const int* __restrict__ etype) {
    int e = blockIdx.x * blockDim.x + threadIdx.x;
    if (e >= NE) return;
    int d = dstv[e];
    int pos = g_off[d] + atomicAdd(&g_cur[d], 1);
    g_eidx[pos] = (srcv[e] << 3) | etype[e];
}

// ================= CSR aggregation: h[d] = relu(root[d] + sum + bias) =================
template <int D>
__global__ void __launch_bounds__(256) agg_kernel(const float* __restrict__ xW,
                                                  const float* __restrict__ rootb,
                                                  const float* __restrict__ bias,
                                                  float* __restrict__ out) {
    constexpr int TPD = D / 4;
    int d = blockIdx.x * (256 / TPD) + threadIdx.x / TPD;
    int c = threadIdx.x % TPD;
    if (d >= NN) return;
    int beg = __ldg(g_off + d), end = __ldg(g_off + d + 1);
    float4 acc = make_float4(0.f, 0.f, 0.f, 0.f);
    int j = beg;
    for (; j + 1 < end; j += 2) {
        int pk0 = __ldg(g_eidx + j), pk1 = __ldg(g_eidx + j + 1);
        float w0 = __ldg(g_inv + d * RREL + (pk0 & 7));
        float w1 = __ldg(g_inv + d * RREL + (pk1 & 7));
        float4 v0 = __ldg((const float4*)(xW + (size_t)pk0 * D) + c);
        float4 v1 = __ldg((const float4*)(xW + (size_t)pk1 * D) + c);
        acc.x = fmaf(w0, v0.x, acc.x); acc.y = fmaf(w0, v0.y, acc.y);
        acc.z = fmaf(w0, v0.z, acc.z); acc.w = fmaf(w0, v0.w, acc.w);
        acc.x = fmaf(w1, v1.x, acc.x); acc.y = fmaf(w1, v1.y, acc.y);
        acc.z = fmaf(w1, v1.z, acc.z); acc.w = fmaf(w1, v1.w, acc.w);
    }
    if (j < end) {
        int pk = __ldg(g_eidx + j);
        float w = __ldg(g_inv + d * RREL + (pk & 7));
        float4 v = __ldg((const float4*)(xW + (size_t)pk * D) + c);
        acc.x = fmaf(w, v.x, acc.x); acc.y = fmaf(w, v.y, acc.y);
        acc.z = fmaf(w, v.z, acc.z); acc.w = fmaf(w, v.w, acc.w);
    }
    float4 base = __ldg((const float4*)(rootb + (size_t)d * D) + c);
    float4 b = __ldg((const float4*)bias + c);
    float4 o;
    o.x = fmaxf(acc.x + base.x + b.x, 0.f);
    o.y = fmaxf(acc.y + base.y + b.y, 0.f);
    o.z = fmaxf(acc.z + base.z + b.z, 0.f);
    o.w = fmaxf(acc.w + base.w + b.w, 0.f);
    *((float4*)(out + (size_t)d * D) + c) = o;
}

// ================= utility =================
__global__ void half_copy_kernel(const float4* __restrict__ src, __half* __restrict__ dst, int n4) {
    int i = blockIdx.x * blockDim.x + threadIdx.x;
    if (i < n4) {
        float4 v = src[i];
        __half* d = dst + (size_t)i * 4;
        ((half2*)d)[0] = __floats2half2_rn(v.x, v.y);
        ((half2*)d)[1] = __floats2half2_rn(v.z, v.w);
    }
}

// ================= launch =================
extern "C" void kernel_launch(void* const* d_in, const int* in_sizes, int n_in,
                              void* d_out, int out_size) {
    const int*   edge_index = (const int*)d_in[0];
    const int*   etype      = (const int*)d_in[1];
    const float* etext      = (const float*)d_in[2];
    const float* node_emb   = (const float*)d_in[3];
    const float* W1         = (const float*)d_in[4];
    const float* root1      = (const float*)d_in[5];
    const float* b1         = (const float*)d_in[6];
    const float* W2         = (const float*)d_in[7];
    const float* root2      = (const float*)d_in[8];
    const float* b2         = (const float*)d_in[9];
    const float* mlpW1      = (const float*)d_in[10];
    const float* mlpb1      = (const float*)d_in[11];
    const float* mlpW2      = (const float*)d_in[12];
    const float* mlpb2      = (const float*)d_in[13];

    const int* srcv = edge_index;
    const int* dstv = edge_index + NE;
    float* logits = (float*)d_out;
    float* h2     = (float*)d_out + NE;

    void* p;
    cudaGetSymbolAddress(&p, g_cnt); int*    cntp = (int*)p;
    cudaGetSymbolAddress(&p, g_cur); int*    curp = (int*)p;
    cudaGetSymbolAddress(&p, g_xW);  float*  xW   = (float*)p;
    cudaGetSymbolAddress(&p, g_agg); float*  agg  = (float*)p;
    cudaGetSymbolAddress(&p, g_h1);  float*  h1   = (float*)p;
    cudaGetSymbolAddress(&p, g_H);   float*  H    = (float*)p;
    cudaGetSymbolAddress(&p, g_wt);  __half* wt   = (__half*)p;

    const int GSMEM = (2 * 128 * ALD + NSTAGE * 16 * BLD) * 2;      // 29696
    const int ESMEM = 64 * 256 * 4;                                  // 65536 (>= staging 39936)
    cudaFuncSetAttribute(twmma_kernel, cudaFuncAttributeMaxDynamicSharedMemorySize, GSMEM);
    cudaFuncSetAttribute(edge_fused_kernel, cudaFuncAttributeMaxDynamicSharedMemorySize, ESMEM);

    // weight conversion to fp16
    half_copy_kernel<<<512, 256>>>((const float4*)W1, wt + OFF_W1, 524288 / 4);
    half_copy_kernel<<<64, 256>>>((const float4*)root1, wt + OFF_R1, 65536 / 4);
    half_copy_kernel<<<256, 256>>>((const float4*)W2, wt + OFF_W2, 262144 / 4);
    half_copy_kernel<<<32, 256>>>((const float4*)root2, wt + OFF_R2, 32768 / 4);
    half_copy_kernel<<<128, 256>>>((const float4*)mlpW1, wt + OFF_M1, 131072 / 4);

    // CSR build
    zeroi_kernel<<<(NN * RREL + 255) / 256, 256>>>(cntp, NN * RREL);
    zeroi_kernel<<<(NN + 255) / 256, 256>>>(curp, NN);
    count_kernel<<<(NE + 255) / 256, 256>>>(dstv, etype);
    inv_deg_kernel<<<(NN + 255) / 256, 256>>>();
    scan_kernel<<<1, 1024>>>();
    fill_kernel<<<(NE + 255) / 256, 256>>>(srcv, dstv, etype);

    const int MB = NP / 128;  // 391

    // ---- layer 1 ----
    twmma_kernel<<<dim3(MB, 2, 8), 256, GSMEM>>>(node_emb, wt + OFF_W1, xW,
                                                 NN, 256, 256, 256, 2048, 65536L, 256L);
    twmma_kernel<<<dim3(MB, 2, 1), 256, GSMEM>>>(node_emb, wt + OFF_R1, agg,
                                                 NN, 256, 256, 256, 256, 0L, 0L);
    agg_kernel<256><<<(NN + 3) / 4, 256>>>(xW, agg, b1, h1);

    // ---- layer 2 ----
    twmma_kernel<<<dim3(MB, 1, 8), 256, GSMEM>>>(h1, wt + OFF_W2, xW,
                                                 NN, 256, 256, 128, 1024, 32768L, 128L);
    twmma_kernel<<<dim3(MB, 1, 1), 256, GSMEM>>>(h1, wt + OFF_R2, agg,
                                                 NN, 256, 256, 128, 128, 0L, 0L);
    agg_kernel<128><<<(NN + 7) / 8, 256>>>(xW, agg, b2, h2);

    // ---- edge MLP: Hs|Hd in one z=2 launch, then fused edge kernel ----
    twmma_kernel<<<dim3(MB, 2, 2), 256, GSMEM>>>(h2, wt + OFF_M1, H,
                                                 NN, 128, 128, 256, 256,
                                                 32768L, (long)NP * 256);
    edge_fused_kernel<<<NE / 64, 256, ESMEM>>>(srcv, dstv, etext, wt + OFF_M1 + 65536,
                                               mlpb1, mlpW2, mlpb2,
                                               H, H + (size_t)NP * 256, logits);
}